// round 2
// baseline (speedup 1.0000x reference)
#include <cuda_runtime.h>
#include <cuda_bf16.h>

#define NN 20000     // nodes
#define EE 500000    // edges
#define DD 256       // feature dim
#define HK 1536      // H row stride: 3*256 etype cols + 3*256 hop cols

// ---------------- scratch (static device memory; no allocs) ----------------
__device__ float g_xs[4][NN * DD];        // xs[0..3]  (~82 MB)
__device__ float g_H[(size_t)NN * HK];    // per-stage message matrix (~123 MB)
__device__ int   g_deg[NN];
__device__ int   g_rowptr[NN + 1];
__device__ int   g_cursor[NN];
__device__ int2  g_edge[EE];              // (src, etype | hop<<2), grouped by dst

// ---------------- CSR build ----------------
__global__ void copy_x_kernel(const float* __restrict__ x) {
    int i = blockIdx.x * blockDim.x + threadIdx.x;
    if (i < NN * DD) g_xs[0][i] = x[i];
}

__global__ void zero_deg_kernel() {
    int i = blockIdx.x * blockDim.x + threadIdx.x;
    if (i < NN) g_deg[i] = 0;
}

__global__ void deg_kernel(const int* __restrict__ ei) {
    int i = blockIdx.x * blockDim.x + threadIdx.x;
    if (i < EE) atomicAdd(&g_deg[ei[EE + i]], 1);
}

// exclusive scan of g_deg (20000 elems), single block of 1024 threads
__global__ void scan_kernel() {
    __shared__ int wsum[32];
    __shared__ int carry_s;
    int tid = threadIdx.x, lane = tid & 31, w = tid >> 5;
    if (tid == 0) carry_s = 0;
    __syncthreads();
    for (int base = 0; base < NN; base += 1024) {
        int i = base + tid;
        int v = (i < NN) ? g_deg[i] : 0;
        int x = v;
        #pragma unroll
        for (int o = 1; o < 32; o <<= 1) {
            int y = __shfl_up_sync(0xffffffffu, x, o);
            if (lane >= o) x += y;
        }
        if (lane == 31) wsum[w] = x;
        __syncthreads();
        if (w == 0) {
            int s = wsum[lane];
            #pragma unroll
            for (int o = 1; o < 32; o <<= 1) {
                int y = __shfl_up_sync(0xffffffffu, s, o);
                if (lane >= o) s += y;
            }
            wsum[lane] = s;
        }
        __syncthreads();
        int excl = carry_s + (w ? wsum[w - 1] : 0) + (x - v);
        if (i < NN) { g_rowptr[i] = excl; g_cursor[i] = excl; }
        int total = wsum[31];
        __syncthreads();
        if (tid == 0) carry_s += total;
        __syncthreads();
    }
    if (tid == 0) g_rowptr[NN] = carry_s;
}

__global__ void fill_kernel(const int* __restrict__ ei, const int* __restrict__ attr) {
    int i = blockIdx.x * blockDim.x + threadIdx.x;
    if (i >= EE) return;
    int src = ei[i];
    int dst = ei[EE + i];
    int hop = attr[2 * i + 0];
    int et  = attr[2 * i + 1];
    int pos = atomicAdd(&g_cursor[dst], 1);
    g_edge[pos] = make_int2(src, et | (hop << 2));
}

// ---------------- GEMM: H[:, col_off:col_off+256] = g_xs[a_idx] @ W + bias ----------------
// BM=64, BN=64, BK=16, 128 threads, thread tile 8(m)x4(n) via packed f32x2 FMA
#define GM_BM 64
#define GM_BN 64
#define GM_BK 16

__global__ __launch_bounds__(128) void gemm_kernel(int a_idx,
                                                   const float* __restrict__ W,
                                                   const float* __restrict__ bias,
                                                   int col_off) {
    __shared__ __align__(16) float As[GM_BK][GM_BM + 2];  // stride 66 (even, conflict-reducing)
    __shared__ __align__(16) float Bs[GM_BK][GM_BN];
    const float* A = g_xs[a_idx];

    int mblk = blockIdx.x * GM_BM;
    int nblk = blockIdx.y * GM_BN;
    int tid  = threadIdx.x;
    int tn = tid & 15, tm = tid >> 4;   // tn: 0..15, tm: 0..7
    int m0 = tm * 8, n0 = tn * 4;

    unsigned long long c2[16];          // 4 m-pairs x 4 n, packed (m even, m odd)
    #pragma unroll
    for (int i = 0; i < 16; i++) c2[i] = 0ull;

    for (int kk = 0; kk < DD; kk += GM_BK) {
        // A tile: 64 rows x 16 cols, store transposed As[k][m]
        #pragma unroll
        for (int l = 0; l < 2; ++l) {
            int f = tid + l * 128;
            int row = f >> 2, cseg = f & 3;
            int gm = mblk + row;
            float4 v = make_float4(0.f, 0.f, 0.f, 0.f);
            if (gm < NN) v = *(const float4*)(A + (size_t)gm * DD + kk + cseg * 4);
            As[cseg * 4 + 0][row] = v.x;
            As[cseg * 4 + 1][row] = v.y;
            As[cseg * 4 + 2][row] = v.z;
            As[cseg * 4 + 3][row] = v.w;
        }
        // B tile: 16 rows x 64 cols
        #pragma unroll
        for (int l = 0; l < 2; ++l) {
            int f = tid + l * 128;
            int row = f >> 4, cseg = f & 15;
            float4 v = *(const float4*)(W + (size_t)(kk + row) * DD + nblk + cseg * 4);
            *(float4*)&Bs[row][cseg * 4] = v;
        }
        __syncthreads();
        #pragma unroll
        for (int k = 0; k < GM_BK; ++k) {
            unsigned long long a2[4], b2[4];
            #pragma unroll
            for (int p = 0; p < 4; p++)
                a2[p] = *(const unsigned long long*)&As[k][m0 + 2 * p];
            #pragma unroll
            for (int j = 0; j < 4; j++) {
                float bv = Bs[k][n0 + j];
                asm("mov.b64 %0, {%1, %1};" : "=l"(b2[j]) : "f"(bv));
            }
            #pragma unroll
            for (int p = 0; p < 4; p++)
                #pragma unroll
                for (int j = 0; j < 4; j++)
                    asm("fma.rn.f32x2 %0, %1, %2, %0;"
                        : "+l"(c2[p * 4 + j]) : "l"(a2[p]), "l"(b2[j]));
        }
        __syncthreads();
    }
    // epilogue: add bias, write to g_H slice
    #pragma unroll
    for (int j = 0; j < 4; j++) {
        float bb = bias[nblk + n0 + j];
        #pragma unroll
        for (int p = 0; p < 4; p++) {
            float lo, hi;
            asm("mov.b64 {%0, %1}, %2;" : "=f"(lo), "=f"(hi) : "l"(c2[p * 4 + j]));
            int r0 = mblk + m0 + 2 * p;
            int col = col_off + nblk + n0 + j;
            if (r0 < NN)     g_H[(size_t)r0 * HK + col]       = lo + bb;
            if (r0 + 1 < NN) g_H[(size_t)(r0 + 1) * HK + col] = hi + bb;
        }
    }
}

// ---------------- aggregation: one block per dst node, one thread per column ----------------
// acc[dst] = sum over in-edges: H[src, etype*256+c]  (+ H[src, 768+(hop-2)*256+c] if 2<=hop<=t+1)
// x_{t+1} = x_t + relu(acc)
__global__ __launch_bounds__(256) void agg_kernel(int t, float* __restrict__ dfinal) {
    int n = blockIdx.x;
    int tid = threadIdx.x;
    int beg = g_rowptr[n], end = g_rowptr[n + 1];
    float acc = 0.0f;
    int hopmax = t + 1;
    for (int i = beg; i < end; ++i) {
        int2 e = g_edge[i];
        const float* hrow = g_H + (size_t)e.x * HK;
        int et  = e.y & 3;
        int hop = e.y >> 2;
        acc += __ldg(&hrow[et * 256 + tid]);
        if (hop >= 2 && hop <= hopmax)
            acc += __ldg(&hrow[768 + (hop - 2) * 256 + tid]);
    }
    float* outp = (t < 3) ? g_xs[t + 1] : dfinal;
    int idx = n * DD + tid;
    outp[idx] = g_xs[t][idx] + fmaxf(acc, 0.0f);
}

// ---------------- driver ----------------
extern "C" void kernel_launch(void* const* d_in, const int* in_sizes, int n_in,
                              void* d_out, int out_size) {
    const float* x      = (const float*)d_in[0];
    const int*   ei     = (const int*)d_in[1];   // [2, E]: row0=src, row1=dst
    const int*   attr   = (const int*)d_in[2];   // [E, 2]: (hop, etype)
    const float* W_edge = (const float*)d_in[3]; // [4,3,256,256]
    const float* b_edge = (const float*)d_in[4]; // [4,3,256]
    const float* W_hop  = (const float*)d_in[5]; // [4,3,256,256]
    const float* b_hop  = (const float*)d_in[6]; // [4,3,256]
    float* out = (float*)d_out;

    copy_x_kernel<<<(NN * DD + 255) / 256, 256>>>(x);
    zero_deg_kernel<<<(NN + 255) / 256, 256>>>();
    deg_kernel<<<(EE + 255) / 256, 256>>>(ei);
    scan_kernel<<<1, 1024>>>();
    fill_kernel<<<(EE + 255) / 256, 256>>>(ei, attr);

    dim3 ggrid((NN + GM_BM - 1) / GM_BM, DD / GM_BN);
    for (int t = 0; t < 4; ++t) {
        // etype GEMMs: A = xs[t], W_edge[t,e] -> H cols [e*256, e*256+256)
        for (int e = 0; e < 3; ++e) {
            gemm_kernel<<<ggrid, 128>>>(t,
                                        W_edge + (size_t)(t * 3 + e) * DD * DD,
                                        b_edge + (size_t)(t * 3 + e) * DD,
                                        e * 256);
        }
        // hop GEMMs: k = 2..t+1, A = xs[t-k+1], W_hop[t,k-2] -> H cols [768+(k-2)*256, ...)
        for (int k = 2; k <= t + 1; ++k) {
            gemm_kernel<<<ggrid, 128>>>(t - k + 1,
                                        W_hop + (size_t)(t * 3 + (k - 2)) * DD * DD,
                                        b_hop + (size_t)(t * 3 + (k - 2)) * DD,
                                        768 + (k - 2) * 256);
        }
        agg_kernel<<<NN, 256>>>(t, out);
    }
}

// round 3
// speedup vs baseline: 2.0572x; 2.0572x over previous
#include <cuda_runtime.h>
#include <cuda_bf16.h>

#define NN 20000     // nodes
#define EE 500000    // edges
#define DD 256       // feature dim
#define HK 1536      // H row stride: 3*256 etype cols + 3*256 hop cols

// ---------------- scratch (static device memory; no allocs) ----------------
__device__ float g_xs[4][NN * DD];        // xs[0..3]  (~82 MB)
__device__ float g_H[(size_t)NN * HK];    // per-stage message matrix (~123 MB)
__device__ int   g_deg[NN];
__device__ int   g_rowptr[NN + 1];
__device__ int   g_cursor[NN];
__device__ int2  g_edge[EE];              // (src, etype | hop<<2), grouped by dst

// ---------------- CSR build ----------------
__global__ void copy_x_kernel(const float* __restrict__ x) {
    int i = blockIdx.x * blockDim.x + threadIdx.x;
    if (i < NN * DD) g_xs[0][i] = x[i];
}

__global__ void zero_deg_kernel() {
    int i = blockIdx.x * blockDim.x + threadIdx.x;
    if (i < NN) g_deg[i] = 0;
}

__global__ void deg_kernel(const int* __restrict__ ei) {
    int i = blockIdx.x * blockDim.x + threadIdx.x;
    if (i < EE) atomicAdd(&g_deg[ei[EE + i]], 1);
}

// exclusive scan of g_deg (20000 elems), single block of 1024 threads
__global__ void scan_kernel() {
    __shared__ int wsum[32];
    __shared__ int carry_s;
    int tid = threadIdx.x, lane = tid & 31, w = tid >> 5;
    if (tid == 0) carry_s = 0;
    __syncthreads();
    for (int base = 0; base < NN; base += 1024) {
        int i = base + tid;
        int v = (i < NN) ? g_deg[i] : 0;
        int x = v;
        #pragma unroll
        for (int o = 1; o < 32; o <<= 1) {
            int y = __shfl_up_sync(0xffffffffu, x, o);
            if (lane >= o) x += y;
        }
        if (lane == 31) wsum[w] = x;
        __syncthreads();
        if (w == 0) {
            int s = wsum[lane];
            #pragma unroll
            for (int o = 1; o < 32; o <<= 1) {
                int y = __shfl_up_sync(0xffffffffu, s, o);
                if (lane >= o) s += y;
            }
            wsum[lane] = s;
        }
        __syncthreads();
        int excl = carry_s + (w ? wsum[w - 1] : 0) + (x - v);
        if (i < NN) { g_rowptr[i] = excl; g_cursor[i] = excl; }
        int total = wsum[31];
        __syncthreads();
        if (tid == 0) carry_s += total;
        __syncthreads();
    }
    if (tid == 0) g_rowptr[NN] = carry_s;
}

__global__ void fill_kernel(const int* __restrict__ ei, const int* __restrict__ attr) {
    int i = blockIdx.x * blockDim.x + threadIdx.x;
    if (i >= EE) return;
    int src = ei[i];
    int dst = ei[EE + i];
    int hop = attr[2 * i + 0];
    int et  = attr[2 * i + 1];
    int pos = atomicAdd(&g_cursor[dst], 1);
    g_edge[pos] = make_int2(src, et | (hop << 2));
}

// ---------------- tf32 tensor-core GEMM ----------------
// H[:, col_off + 256*e + n] = g_xs[a_idx] @ W[e] + bias[e], for e = n-block group.
// BM=128, BN=128, BK=16, 256 threads (8 warps: 4 in m x 2 in n), warp tile 32x64,
// mma.sync.m16n8k8.f32.tf32.tf32.f32, fp32 accumulate. cvt.rna.tf32 on smem fill.

__device__ __forceinline__ unsigned f2tf32(float f) {
    unsigned u;
    asm("cvt.rna.tf32.f32 %0, %1;" : "=r"(u) : "f"(f));
    return u;
}

#define TBM 128
#define TBN 128
#define TBK 16
#define AS_LD 20    // padded stride for As[128][20] (conflict-free fragment loads)
#define BS_LD 136   // padded stride for Bs[16][136]

__global__ __launch_bounds__(256) void gemm_tc_kernel(int a_idx,
                                                      const float* __restrict__ Wbase,
                                                      const float* __restrict__ biasbase,
                                                      int col_off) {
    __shared__ __align__(16) unsigned As[TBM * AS_LD];   // As[row][k], tf32 bits
    __shared__ __align__(16) unsigned Bs[TBK * BS_LD];   // Bs[k][n],  tf32 bits

    const float* A = g_xs[a_idx];
    int mblk = blockIdx.x * TBM;
    int nblk = blockIdx.y * TBN;                 // within the concatenated N
    int eg   = nblk >> 8;                        // which 256-col weight group
    int nloc = nblk & 255;                       // local col within that group
    const float* W    = Wbase + (size_t)eg * DD * DD;   // [256][256] row-major
    const float* bias = biasbase + (size_t)eg * DD;

    int tid  = threadIdx.x;
    int wid  = tid >> 5;
    int lane = tid & 31;
    int wm   = wid & 3;            // 0..3  -> m offset wm*32
    int wn   = wid >> 2;           // 0..1  -> n offset wn*64
    int g    = lane >> 2;          // 0..7
    int tq   = lane & 3;           // 0..3

    float c[2][8][4];
    #pragma unroll
    for (int mt = 0; mt < 2; mt++)
        #pragma unroll
        for (int nt = 0; nt < 8; nt++)
            #pragma unroll
            for (int i = 0; i < 4; i++) c[mt][nt][i] = 0.f;

    for (int kk = 0; kk < DD; kk += TBK) {
        // --- fill As: 128 rows x 16 cols ---
        #pragma unroll
        for (int l = 0; l < 2; ++l) {
            int f = tid + l * 256;          // float4 index, 0..511
            int row = f >> 2, cseg = f & 3;
            int gm = mblk + row;
            float4 v = make_float4(0.f, 0.f, 0.f, 0.f);
            if (gm < NN) v = *(const float4*)(A + (size_t)gm * DD + kk + cseg * 4);
            unsigned* dst = &As[row * AS_LD + cseg * 4];
            dst[0] = f2tf32(v.x); dst[1] = f2tf32(v.y);
            dst[2] = f2tf32(v.z); dst[3] = f2tf32(v.w);
        }
        // --- fill Bs: 16 rows x 128 cols ---
        #pragma unroll
        for (int l = 0; l < 2; ++l) {
            int f = tid + l * 256;
            int row = f >> 5, cseg = f & 31;
            float4 v = *(const float4*)(W + (size_t)(kk + row) * DD + nloc + cseg * 4);
            unsigned* dst = &Bs[row * BS_LD + cseg * 4];
            dst[0] = f2tf32(v.x); dst[1] = f2tf32(v.y);
            dst[2] = f2tf32(v.z); dst[3] = f2tf32(v.w);
        }
        __syncthreads();

        #pragma unroll
        for (int kc = 0; kc < 2; ++kc) {      // two k-chunks of 8
            int k0 = kc * 8;
            // A fragments for both 16-row m-tiles
            unsigned a[2][4];
            #pragma unroll
            for (int mt = 0; mt < 2; mt++) {
                int r = wm * 32 + mt * 16 + g;
                a[mt][0] = As[r * AS_LD + k0 + tq];
                a[mt][1] = As[(r + 8) * AS_LD + k0 + tq];
                a[mt][2] = As[r * AS_LD + k0 + tq + 4];
                a[mt][3] = As[(r + 8) * AS_LD + k0 + tq + 4];
            }
            #pragma unroll
            for (int nt = 0; nt < 8; nt++) {
                int nb = wn * 64 + nt * 8;
                unsigned b0 = Bs[(k0 + tq) * BS_LD + nb + g];
                unsigned b1 = Bs[(k0 + tq + 4) * BS_LD + nb + g];
                #pragma unroll
                for (int mt = 0; mt < 2; mt++) {
                    asm volatile(
                        "mma.sync.aligned.m16n8k8.row.col.f32.tf32.tf32.f32 "
                        "{%0,%1,%2,%3}, {%4,%5,%6,%7}, {%8,%9}, {%0,%1,%2,%3};\n"
                        : "+f"(c[mt][nt][0]), "+f"(c[mt][nt][1]),
                          "+f"(c[mt][nt][2]), "+f"(c[mt][nt][3])
                        : "r"(a[mt][0]), "r"(a[mt][1]), "r"(a[mt][2]), "r"(a[mt][3]),
                          "r"(b0), "r"(b1));
                }
            }
        }
        __syncthreads();
    }

    // --- epilogue: bias + store into g_H slice ---
    #pragma unroll
    for (int nt = 0; nt < 8; nt++) {
        int coll = nloc + wn * 64 + nt * 8 + 2 * tq;          // local col in group
        int colg = col_off + (eg << 8) + coll;                 // col in H
        float b0 = __ldg(&bias[coll]);
        float b1 = __ldg(&bias[coll + 1]);
        #pragma unroll
        for (int mt = 0; mt < 2; mt++) {
            int r0 = mblk + wm * 32 + mt * 16 + g;
            if (r0 < NN) {
                float2 v = make_float2(c[mt][nt][0] + b0, c[mt][nt][1] + b1);
                *(float2*)&g_H[(size_t)r0 * HK + colg] = v;
            }
            int r1 = r0 + 8;
            if (r1 < NN) {
                float2 v = make_float2(c[mt][nt][2] + b0, c[mt][nt][3] + b1);
                *(float2*)&g_H[(size_t)r1 * HK + colg] = v;
            }
        }
    }
}

// ---------------- aggregation: one block per dst node, one thread per column ----------------
__global__ __launch_bounds__(256) void agg_kernel(int t, float* __restrict__ dfinal) {
    int n = blockIdx.x;
    int tid = threadIdx.x;
    int beg = g_rowptr[n], end = g_rowptr[n + 1];
    float acc = 0.0f;
    int hopmax = t + 1;
    for (int i = beg; i < end; ++i) {
        int2 e = g_edge[i];
        const float* hrow = g_H + (size_t)e.x * HK;
        int et  = e.y & 3;
        int hop = e.y >> 2;
        acc += __ldg(&hrow[et * 256 + tid]);
        if (hop >= 2 && hop <= hopmax)
            acc += __ldg(&hrow[768 + (hop - 2) * 256 + tid]);
    }
    float* outp = (t < 3) ? g_xs[t + 1] : dfinal;
    int idx = n * DD + tid;
    outp[idx] = g_xs[t][idx] + fmaxf(acc, 0.0f);
}

// ---------------- driver ----------------
extern "C" void kernel_launch(void* const* d_in, const int* in_sizes, int n_in,
                              void* d_out, int out_size) {
    const float* x      = (const float*)d_in[0];
    const int*   ei     = (const int*)d_in[1];   // [2, E]: row0=src, row1=dst
    const int*   attr   = (const int*)d_in[2];   // [E, 2]: (hop, etype)
    const float* W_edge = (const float*)d_in[3]; // [4,3,256,256]
    const float* b_edge = (const float*)d_in[4]; // [4,3,256]
    const float* W_hop  = (const float*)d_in[5]; // [4,3,256,256]
    const float* b_hop  = (const float*)d_in[6]; // [4,3,256]
    float* out = (float*)d_out;

    copy_x_kernel<<<(NN * DD + 255) / 256, 256>>>(x);
    zero_deg_kernel<<<(NN + 255) / 256, 256>>>();
    deg_kernel<<<(EE + 255) / 256, 256>>>(ei);
    scan_kernel<<<1, 1024>>>();
    fill_kernel<<<(EE + 255) / 256, 256>>>(ei, attr);

    int mgrid = (NN + TBM - 1) / TBM;            // 157
    for (int t = 0; t < 4; ++t) {
        // fused etype GEMMs: A = xs[t], W_edge[t,0..2] -> H cols [0, 768)
        {
            dim3 grid(mgrid, 3 * DD / TBN);      // 157 x 6
            gemm_tc_kernel<<<grid, 256>>>(t,
                                          W_edge + (size_t)(t * 3) * DD * DD,
                                          b_edge + (size_t)(t * 3) * DD,
                                          0);
        }
        // hop GEMMs: k = 2..t+1, A = xs[t-k+1], W_hop[t,k-2] -> H cols [768+(k-2)*256, ...)
        for (int k = 2; k <= t + 1; ++k) {
            dim3 grid(mgrid, DD / TBN);          // 157 x 2
            gemm_tc_kernel<<<grid, 256>>>(t - k + 1,
                                          W_hop + (size_t)(t * 3 + (k - 2)) * DD * DD,
                                          b_hop + (size_t)(t * 3 + (k - 2)) * DD,
                                          768 + (k - 2) * 256);
        }
        agg_kernel<<<NN, 256>>>(t, out);
    }
}

// round 4
// speedup vs baseline: 2.5486x; 1.2389x over previous
#include <cuda_runtime.h>
#include <cuda_bf16.h>

#define NN 20000     // nodes
#define NP 20096     // padded rows (multiple of 128) for GEMM tile overrun safety
#define EE 500000    // edges
#define DD 256       // feature dim
#define SK 1536      // S row stride: 3 etype buckets + 3 hop buckets, 256 cols each

// ---------------- scratch (static device memory; no allocs) ----------------
__device__ float    g_xs[4][NN * DD];            // xs[0..3]
__device__ unsigned g_S[(size_t)NP * SK];        // bucketed segment sums, tf32 bits
__device__ unsigned g_We[12 * DD * DD];          // W_edge pre-converted to tf32 bits
__device__ unsigned g_Wh[12 * DD * DD];          // W_hop  pre-converted to tf32 bits
__device__ int      g_deg[NN];
__device__ int      g_rowptr[NN + 1];
__device__ int      g_cursor[NN];
__device__ int      g_cnt[NN * 8];               // per-node bucket counts (6 used)
__device__ int2     g_edge[EE];                  // (src, etype | hop<<2), grouped by dst

__device__ __forceinline__ unsigned f2tf32(float f) {
    unsigned u;
    asm("cvt.rna.tf32.f32 %0, %1;" : "=r"(u) : "f"(f));
    return u;
}

// ---------------- setup kernels ----------------
__global__ void copy_x_kernel(const float* __restrict__ x) {
    int i = blockIdx.x * blockDim.x + threadIdx.x;
    if (i < NN * DD) g_xs[0][i] = x[i];
}

__global__ void conv_w_kernel(const float* __restrict__ We, const float* __restrict__ Wh) {
    int i = blockIdx.x * blockDim.x + threadIdx.x;
    if (i < 12 * DD * DD) {
        g_We[i] = f2tf32(We[i]);
        g_Wh[i] = f2tf32(Wh[i]);
    }
}

__global__ void zero_meta_kernel() {
    int i = blockIdx.x * blockDim.x + threadIdx.x;
    if (i < NN) g_deg[i] = 0;
    if (i < NN * 8) g_cnt[i] = 0;
}

__global__ void deg_kernel(const int* __restrict__ ei) {
    int i = blockIdx.x * blockDim.x + threadIdx.x;
    if (i < EE) atomicAdd(&g_deg[ei[EE + i]], 1);
}

// exclusive scan of g_deg (20000 elems), single block of 1024 threads
__global__ void scan_kernel() {
    __shared__ int wsum[32];
    __shared__ int carry_s;
    int tid = threadIdx.x, lane = tid & 31, w = tid >> 5;
    if (tid == 0) carry_s = 0;
    __syncthreads();
    for (int base = 0; base < NN; base += 1024) {
        int i = base + tid;
        int v = (i < NN) ? g_deg[i] : 0;
        int x = v;
        #pragma unroll
        for (int o = 1; o < 32; o <<= 1) {
            int y = __shfl_up_sync(0xffffffffu, x, o);
            if (lane >= o) x += y;
        }
        if (lane == 31) wsum[w] = x;
        __syncthreads();
        if (w == 0) {
            int s = wsum[lane];
            #pragma unroll
            for (int o = 1; o < 32; o <<= 1) {
                int y = __shfl_up_sync(0xffffffffu, s, o);
                if (lane >= o) s += y;
            }
            wsum[lane] = s;
        }
        __syncthreads();
        int excl = carry_s + (w ? wsum[w - 1] : 0) + (x - v);
        if (i < NN) { g_rowptr[i] = excl; g_cursor[i] = excl; }
        int total = wsum[31];
        __syncthreads();
        if (tid == 0) carry_s += total;
        __syncthreads();
    }
    if (tid == 0) g_rowptr[NN] = carry_s;
}

__global__ void fill_kernel(const int* __restrict__ ei, const int* __restrict__ attr) {
    int i = blockIdx.x * blockDim.x + threadIdx.x;
    if (i >= EE) return;
    int src = ei[i];
    int dst = ei[EE + i];
    int hop = attr[2 * i + 0];
    int et  = attr[2 * i + 1];
    int pos = atomicAdd(&g_cursor[dst], 1);
    g_edge[pos] = make_int2(src, et | (hop << 2));
    atomicAdd(&g_cnt[dst * 8 + et], 1);
    if (hop >= 2) atomicAdd(&g_cnt[dst * 8 + 3 + (hop - 2)], 1);
}

// ---------------- aggregation (gather-sum of x rows into buckets) ----------------
// One block per dst node, 128 threads, float2 per thread (2 cols).
// etype bucket b: S[n, b*256+c]      = sum_{edges et==b}  xs[t][src, c]
// hop   bucket j: S[n, 768+j*256+c] = sum_{edges hop==j+2} xs[t-1-j][src, c]
// Written as tf32 bits for the cp.async GEMM.
__global__ __launch_bounds__(128) void agg_kernel(int t) {
    int n = blockIdx.x;
    int tid = threadIdx.x;
    int beg = g_rowptr[n], end = g_rowptr[n + 1];
    const float* xt = g_xs[t];
    const float* x1 = (t >= 1) ? g_xs[t - 1] : g_xs[0];
    const float* x2 = (t >= 2) ? g_xs[t - 2] : g_xs[0];
    const float* x3 = (t >= 3) ? g_xs[t - 3] : g_xs[0];
    int nhop = t;

    float2 a0 = {0.f, 0.f}, a1 = {0.f, 0.f}, a2 = {0.f, 0.f};
    float2 h0 = {0.f, 0.f}, h1 = {0.f, 0.f}, h2 = {0.f, 0.f};

    for (int i = beg; i < end; ++i) {
        int2 e = g_edge[i];
        int src = e.x;
        int et  = e.y & 3;
        int hop = e.y >> 2;
        size_t off = (size_t)src * DD + 2 * tid;
        float2 v = *(const float2*)(xt + off);
        if (et == 0)      { a0.x += v.x; a0.y += v.y; }
        else if (et == 1) { a1.x += v.x; a1.y += v.y; }
        else              { a2.x += v.x; a2.y += v.y; }
        if (hop == 2 && nhop >= 1) {
            float2 w = *(const float2*)(x1 + off);
            h0.x += w.x; h0.y += w.y;
        } else if (hop == 3 && nhop >= 2) {
            float2 w = *(const float2*)(x2 + off);
            h1.x += w.x; h1.y += w.y;
        } else if (hop == 4 && nhop >= 3) {
            float2 w = *(const float2*)(x3 + off);
            h2.x += w.x; h2.y += w.y;
        }
    }

    unsigned* srow = g_S + (size_t)n * SK;
    uint2* p;
    p = (uint2*)(srow + 0 * 256 + 2 * tid); *p = make_uint2(f2tf32(a0.x), f2tf32(a0.y));
    p = (uint2*)(srow + 1 * 256 + 2 * tid); *p = make_uint2(f2tf32(a1.x), f2tf32(a1.y));
    p = (uint2*)(srow + 2 * 256 + 2 * tid); *p = make_uint2(f2tf32(a2.x), f2tf32(a2.y));
    if (nhop >= 1) { p = (uint2*)(srow + 768 + 0 * 256 + 2 * tid); *p = make_uint2(f2tf32(h0.x), f2tf32(h0.y)); }
    if (nhop >= 2) { p = (uint2*)(srow + 768 + 1 * 256 + 2 * tid); *p = make_uint2(f2tf32(h1.x), f2tf32(h1.y)); }
    if (nhop >= 3) { p = (uint2*)(srow + 768 + 2 * 256 + 2 * tid); *p = make_uint2(f2tf32(h2.x), f2tf32(h2.y)); }
}

// ---------------- tf32 tensor-core GEMM with cp.async double buffering ----------------
// out[n, col] = x_t[n, col] + relu( (S[n,:kt] @ W_cat[:kt, col]) + sum_b cnt[n,b]*bias_b[col] )
// BM=128, BN=128, BK=16, 256 threads (8 warps: 4m x 2n), warp tile 32x64, m16n8k8 tf32.

#define TBM 128
#define TBN 128
#define TBK 16
#define AS_LD 20    // padded row stride (words) for As[128][20]
#define BS_LD 136   // padded row stride (words) for Bs[16][136]

__device__ __forceinline__ void cp16(void* dst_smem, const void* src) {
    unsigned d = (unsigned)__cvta_generic_to_shared(dst_smem);
    asm volatile("cp.async.ca.shared.global [%0], [%1], 16;" :: "r"(d), "l"(src));
}
#define CP_COMMIT()  asm volatile("cp.async.commit_group;")
#define CP_WAIT(n)   asm volatile("cp.async.wait_group %0;" :: "n"(n))

__global__ __launch_bounds__(256) void gemm_tc_kernel(int t, int kt, int nhop,
                                                      const float* __restrict__ be_all,
                                                      const float* __restrict__ bh_all,
                                                      float* __restrict__ dfinal) {
    __shared__ __align__(16) unsigned As[2][TBM * AS_LD];
    __shared__ __align__(16) unsigned Bs[2][TBK * BS_LD];

    const unsigned* We_t = g_We + (size_t)t * 3 * DD * DD;   // [k_cat][col], k_cat<768
    const unsigned* Wh_t = g_Wh + (size_t)t * 3 * DD * DD;   // [k_cat-768][col]
    const float* be = be_all + (size_t)t * 3 * DD;           // [3][256]
    const float* bh = bh_all + (size_t)t * 3 * DD;           // [3][256]
    const float* xin = g_xs[t];
    float* xout = (t < 3) ? g_xs[t + 1] : dfinal;

    int mblk = blockIdx.x * TBM;
    int nblk = blockIdx.y * TBN;
    int tid  = threadIdx.x;
    int wid  = tid >> 5;
    int lane = tid & 31;
    int wm   = wid & 3;
    int wn   = wid >> 2;
    int g    = lane >> 2;
    int tq   = lane & 3;

    float c[2][8][4];
    #pragma unroll
    for (int mt = 0; mt < 2; mt++)
        #pragma unroll
        for (int nt = 0; nt < 8; nt++)
            #pragma unroll
            for (int i = 0; i < 4; i++) c[mt][nt][i] = 0.f;

    int niter = kt / TBK;

    // --- async tile loader: A 128x16 (512 chunks), B 16x128 (512 chunks) ---
    auto issue = [&](int buf, int kk) {
        const unsigned* Bbase = (kk < 768) ? (We_t + (size_t)kk * DD)
                                           : (Wh_t + (size_t)(kk - 768) * DD);
        #pragma unroll
        for (int l = 0; l < 2; ++l) {
            int ca = tid + l * 256;
            int arow = ca >> 2, aseg = ca & 3;
            cp16(&As[buf][arow * AS_LD + aseg * 4],
                 g_S + (size_t)(mblk + arow) * SK + kk + aseg * 4);
            int cb = tid + l * 256;
            int brow = cb >> 5, bseg = cb & 31;
            cp16(&Bs[buf][brow * BS_LD + bseg * 4],
                 Bbase + (size_t)brow * DD + nblk + bseg * 4);
        }
    };

    issue(0, 0);
    CP_COMMIT();

    for (int i = 0; i < niter; ++i) {
        int cur = i & 1;
        if (i + 1 < niter) {
            issue(cur ^ 1, (i + 1) * TBK);
            CP_COMMIT();
            CP_WAIT(1);
        } else {
            CP_WAIT(0);
        }
        __syncthreads();

        #pragma unroll
        for (int kc = 0; kc < 2; ++kc) {
            int k0 = kc * 8;
            unsigned a[2][4];
            #pragma unroll
            for (int mt = 0; mt < 2; mt++) {
                int r = wm * 32 + mt * 16 + g;
                a[mt][0] = As[cur][r * AS_LD + k0 + tq];
                a[mt][1] = As[cur][(r + 8) * AS_LD + k0 + tq];
                a[mt][2] = As[cur][r * AS_LD + k0 + tq + 4];
                a[mt][3] = As[cur][(r + 8) * AS_LD + k0 + tq + 4];
            }
            #pragma unroll
            for (int nt = 0; nt < 8; nt++) {
                int nb = wn * 64 + nt * 8;
                unsigned b0 = Bs[cur][(k0 + tq) * BS_LD + nb + g];
                unsigned b1 = Bs[cur][(k0 + tq + 4) * BS_LD + nb + g];
                #pragma unroll
                for (int mt = 0; mt < 2; mt++) {
                    asm volatile(
                        "mma.sync.aligned.m16n8k8.row.col.f32.tf32.tf32.f32 "
                        "{%0,%1,%2,%3}, {%4,%5,%6,%7}, {%8,%9}, {%0,%1,%2,%3};\n"
                        : "+f"(c[mt][nt][0]), "+f"(c[mt][nt][1]),
                          "+f"(c[mt][nt][2]), "+f"(c[mt][nt][3])
                        : "r"(a[mt][0]), "r"(a[mt][1]), "r"(a[mt][2]), "r"(a[mt][3]),
                          "r"(b0), "r"(b1));
                }
            }
        }
        __syncthreads();
    }

    // --- epilogue: bias via counts, relu, residual, store ---
    #pragma unroll
    for (int nt = 0; nt < 8; nt++) {
        int col = nblk + wn * 64 + nt * 8 + 2 * tq;
        // per-column bias rows
        float be0c0 = be[0 * DD + col],     be0c1 = be[0 * DD + col + 1];
        float be1c0 = be[1 * DD + col],     be1c1 = be[1 * DD + col + 1];
        float be2c0 = be[2 * DD + col],     be2c1 = be[2 * DD + col + 1];
        float bh0c0 = 0.f, bh0c1 = 0.f, bh1c0 = 0.f, bh1c1 = 0.f, bh2c0 = 0.f, bh2c1 = 0.f;
        if (nhop >= 1) { bh0c0 = bh[0 * DD + col]; bh0c1 = bh[0 * DD + col + 1]; }
        if (nhop >= 2) { bh1c0 = bh[1 * DD + col]; bh1c1 = bh[1 * DD + col + 1]; }
        if (nhop >= 3) { bh2c0 = bh[2 * DD + col]; bh2c1 = bh[2 * DD + col + 1]; }
        #pragma unroll
        for (int mt = 0; mt < 2; mt++) {
            #pragma unroll
            for (int half = 0; half < 2; half++) {
                int r = mblk + wm * 32 + mt * 16 + g + half * 8;
                if (r >= NN) continue;
                const int* cn = g_cnt + r * 8;
                float f0 = (float)cn[0], f1 = (float)cn[1], f2 = (float)cn[2];
                float f3 = (float)cn[3], f4 = (float)cn[4], f5 = (float)cn[5];
                float bias0 = f0 * be0c0 + f1 * be1c0 + f2 * be2c0
                            + f3 * bh0c0 + f4 * bh1c0 + f5 * bh2c0;
                float bias1 = f0 * be0c1 + f1 * be1c1 + f2 * be2c1
                            + f3 * bh0c1 + f4 * bh1c1 + f5 * bh2c1;
                float v0 = c[mt][nt][half * 2 + 0] + bias0;
                float v1 = c[mt][nt][half * 2 + 1] + bias1;
                float2 xr = *(const float2*)(xin + (size_t)r * DD + col);
                float2 o;
                o.x = xr.x + fmaxf(v0, 0.f);
                o.y = xr.y + fmaxf(v1, 0.f);
                *(float2*)(xout + (size_t)r * DD + col) = o;
            }
        }
    }
}

// ---------------- driver ----------------
extern "C" void kernel_launch(void* const* d_in, const int* in_sizes, int n_in,
                              void* d_out, int out_size) {
    const float* x      = (const float*)d_in[0];
    const int*   ei     = (const int*)d_in[1];   // [2, E]: row0=src, row1=dst
    const int*   attr   = (const int*)d_in[2];   // [E, 2]: (hop, etype)
    const float* W_edge = (const float*)d_in[3]; // [4,3,256,256]
    const float* b_edge = (const float*)d_in[4]; // [4,3,256]
    const float* W_hop  = (const float*)d_in[5]; // [4,3,256,256]
    const float* b_hop  = (const float*)d_in[6]; // [4,3,256]
    float* out = (float*)d_out;

    copy_x_kernel<<<(NN * DD + 255) / 256, 256>>>(x);
    conv_w_kernel<<<(12 * DD * DD + 255) / 256, 256>>>(W_edge, W_hop);
    zero_meta_kernel<<<(NN * 8 + 255) / 256, 256>>>();
    deg_kernel<<<(EE + 255) / 256, 256>>>(ei);
    scan_kernel<<<1, 1024>>>();
    fill_kernel<<<(EE + 255) / 256, 256>>>(ei, attr);

    dim3 ggrid((NP + TBM - 1) / TBM, DD / TBN);   // 157 x 2
    for (int t = 0; t < 4; ++t) {
        agg_kernel<<<NN, 128>>>(t);
        int kt = 768 + 256 * t;
        gemm_tc_kernel<<<ggrid, 256>>>(t, kt, t, b_edge, b_hop, out);
    }
}

// round 5
// speedup vs baseline: 2.8250x; 1.1085x over previous
#include <cuda_runtime.h>
#include <cuda_bf16.h>

#define NN 20000     // nodes
#define NP 20096     // padded rows (multiple of 128)
#define EE 500000    // edges
#define DD 256       // feature dim
#define SK 1552      // S row stride: 3 etype + 3 hop buckets (256 each) + 16 cnt/pad cols
#define WROWS 1552   // Wcat rows per stage

// ---------------- scratch (static device memory; no allocs) ----------------
__device__ float    g_xs[4][NN * DD];            // xs[0..3], contiguous
__device__ unsigned g_S[(size_t)NP * SK];        // bucketed segment sums + counts, tf32 bits
__device__ unsigned g_Wcat[4][WROWS * DD];       // packed per-stage weights+bias, tf32 bits
__device__ int      g_deg[NN];
__device__ int      g_rowptr[NN + 1];
__device__ int      g_cursor[NN];
__device__ int      g_cnt[NN * 8];               // per-node bucket counts (6 used)
__device__ int2     g_edge[EE];                  // (src, etype | hop<<2), grouped by dst

__device__ __forceinline__ unsigned f2tf32(float f) {
    unsigned u;
    asm("cvt.rna.tf32.f32 %0, %1;" : "=r"(u) : "f"(f));
    return u;
}

// ---------------- setup ----------------
// copy x into xs[0] + zero deg/cnt
__global__ void setup_kernel(const float* __restrict__ x) {
    int i = blockIdx.x * blockDim.x + threadIdx.x;
    if (i < NN * DD) g_xs[0][i] = x[i];
    if (i < NN) g_deg[i] = 0;
    if (i < NN * 8) g_cnt[i] = 0;
}

// build Wcat[t]: rows [0,768)=W_edge[t]; [768,768+256t)=W_hop[t,j<t];
// [768+256t, +6)=bias rows (be0..2, bh0..2 with j>=t zeroed); rest zero.
__global__ void pack_w_kernel(const float* __restrict__ We, const float* __restrict__ be,
                              const float* __restrict__ Wh, const float* __restrict__ bh) {
    int idx = blockIdx.x * blockDim.x + threadIdx.x;
    if (idx >= 4 * WROWS * DD) return;
    int t = idx / (WROWS * DD);
    int rem = idx - t * (WROWS * DD);
    int r = rem / DD;
    int c = rem - r * DD;
    float v = 0.f;
    int biasr = 768 + 256 * t;
    if (r < 768) {
        v = We[(size_t)((t * 3 + (r >> 8)) * 256 + (r & 255)) * DD + c];
    } else if (r < biasr) {
        int j = (r - 768) >> 8, k = (r - 768) & 255;
        v = Wh[(size_t)((t * 3 + j) * 256 + k) * DD + c];
    } else if (r < biasr + 6) {
        int b = r - biasr;
        if (b < 3) v = be[(size_t)(t * 3 + b) * DD + c];
        else if (b - 3 < t) v = bh[(size_t)(t * 3 + (b - 3)) * DD + c];
    }
    g_Wcat[t][r * DD + c] = f2tf32(v);
}

__global__ void deg_kernel(const int* __restrict__ ei) {
    int i = blockIdx.x * blockDim.x + threadIdx.x;
    if (i < EE) atomicAdd(&g_deg[ei[EE + i]], 1);
}

// exclusive scan of g_deg, single block of 1024 threads
__global__ void scan_kernel() {
    __shared__ int wsum[32];
    __shared__ int carry_s;
    int tid = threadIdx.x, lane = tid & 31, w = tid >> 5;
    if (tid == 0) carry_s = 0;
    __syncthreads();
    for (int base = 0; base < NN; base += 1024) {
        int i = base + tid;
        int v = (i < NN) ? g_deg[i] : 0;
        int x = v;
        #pragma unroll
        for (int o = 1; o < 32; o <<= 1) {
            int y = __shfl_up_sync(0xffffffffu, x, o);
            if (lane >= o) x += y;
        }
        if (lane == 31) wsum[w] = x;
        __syncthreads();
        if (w == 0) {
            int s = wsum[lane];
            #pragma unroll
            for (int o = 1; o < 32; o <<= 1) {
                int y = __shfl_up_sync(0xffffffffu, s, o);
                if (lane >= o) s += y;
            }
            wsum[lane] = s;
        }
        __syncthreads();
        int excl = carry_s + (w ? wsum[w - 1] : 0) + (x - v);
        if (i < NN) { g_rowptr[i] = excl; g_cursor[i] = excl; }
        int total = wsum[31];
        __syncthreads();
        if (tid == 0) carry_s += total;
        __syncthreads();
    }
    if (tid == 0) g_rowptr[NN] = carry_s;
}

__global__ void fill_kernel(const int* __restrict__ ei, const int* __restrict__ attr) {
    int i = blockIdx.x * blockDim.x + threadIdx.x;
    if (i >= EE) return;
    int src = ei[i];
    int dst = ei[EE + i];
    int hop = attr[2 * i + 0];
    int et  = attr[2 * i + 1];
    int pos = atomicAdd(&g_cursor[dst], 1);
    g_edge[pos] = make_int2(src, et | (hop << 2));
    atomicAdd(&g_cnt[dst * 8 + et], 1);
    if (hop >= 2) atomicAdd(&g_cnt[dst * 8 + 3 + (hop - 2)], 1);
}

// ---------------- aggregation ----------------
// 4 nodes per block, 1 warp-pair (64 threads) per node, float4 per thread.
// All branch conditions are per-edge -> warp-uniform (one node per warp group).
__device__ __forceinline__ void st4(unsigned* p, float4 v) {
    *(uint4*)p = make_uint4(f2tf32(v.x), f2tf32(v.y), f2tf32(v.z), f2tf32(v.w));
}
__device__ __forceinline__ void acc4(float4& a, float4 v) {
    a.x += v.x; a.y += v.y; a.z += v.z; a.w += v.w;
}

__global__ __launch_bounds__(256) void agg_kernel(int t) {
    int sub = threadIdx.x >> 6;
    int n = blockIdx.x * 4 + sub;
    if (n >= NN) return;
    int c0 = (threadIdx.x & 63) << 2;     // this thread's 4 columns
    int beg = g_rowptr[n], end = g_rowptr[n + 1];
    const float* xt = g_xs[t];
    const float* xb = g_xs[0];            // base; delayed array j = xb + (t-1-j)*NN*DD
    unsigned tu = (unsigned)t;

    float4 z = {0.f, 0.f, 0.f, 0.f};
    float4 a0 = z, a1 = z, a2 = z, h0 = z, h1 = z, h2 = z;

    int i = beg;
    for (; i + 2 <= end; i += 2) {
        int2 e0 = g_edge[i];
        int2 e1 = g_edge[i + 1];
        float4 v0 = *(const float4*)(xt + (size_t)e0.x * DD + c0);
        float4 v1 = *(const float4*)(xt + (size_t)e1.x * DD + c0);
        int j0 = (e0.y >> 2) - 2, j1 = (e1.y >> 2) - 2;
        bool hb0 = (unsigned)j0 < tu, hb1 = (unsigned)j1 < tu;
        float4 w0 = z, w1 = z;
        if (hb0) w0 = *(const float4*)(xb + (size_t)(t - 1 - j0) * (NN * DD) + (size_t)e0.x * DD + c0);
        if (hb1) w1 = *(const float4*)(xb + (size_t)(t - 1 - j1) * (NN * DD) + (size_t)e1.x * DD + c0);
        int et0 = e0.y & 3, et1 = e1.y & 3;
        if (et0 == 0) acc4(a0, v0); else if (et0 == 1) acc4(a1, v0); else acc4(a2, v0);
        if (et1 == 0) acc4(a0, v1); else if (et1 == 1) acc4(a1, v1); else acc4(a2, v1);
        if (hb0) { if (j0 == 0) acc4(h0, w0); else if (j0 == 1) acc4(h1, w0); else acc4(h2, w0); }
        if (hb1) { if (j1 == 0) acc4(h0, w1); else if (j1 == 1) acc4(h1, w1); else acc4(h2, w1); }
    }
    if (i < end) {
        int2 e0 = g_edge[i];
        float4 v0 = *(const float4*)(xt + (size_t)e0.x * DD + c0);
        int j0 = (e0.y >> 2) - 2;
        bool hb0 = (unsigned)j0 < tu;
        float4 w0 = z;
        if (hb0) w0 = *(const float4*)(xb + (size_t)(t - 1 - j0) * (NN * DD) + (size_t)e0.x * DD + c0);
        int et0 = e0.y & 3;
        if (et0 == 0) acc4(a0, v0); else if (et0 == 1) acc4(a1, v0); else acc4(a2, v0);
        if (hb0) { if (j0 == 0) acc4(h0, w0); else if (j0 == 1) acc4(h1, w0); else acc4(h2, w0); }
    }

    unsigned* srow = g_S + (size_t)n * SK;
    st4(srow + 0 * 256 + c0, a0);
    st4(srow + 1 * 256 + c0, a1);
    st4(srow + 2 * 256 + c0, a2);
    if (t >= 1) st4(srow + 768 + c0, h0);
    if (t >= 2) st4(srow + 1024 + c0, h1);
    if (t >= 3) st4(srow + 1280 + c0, h2);
    // counts + zero pad at cols [768+256t, 768+256t+16)
    int lane = threadIdx.x & 63;
    if (lane < 4) {
        int cc = lane * 4;
        uint4 u;
        u.x = (cc + 0 < 6) ? f2tf32((float)g_cnt[n * 8 + cc + 0]) : 0u;
        u.y = (cc + 1 < 6) ? f2tf32((float)g_cnt[n * 8 + cc + 1]) : 0u;
        u.z = (cc + 2 < 6) ? f2tf32((float)g_cnt[n * 8 + cc + 2]) : 0u;
        u.w = (cc + 3 < 6) ? f2tf32((float)g_cnt[n * 8 + cc + 3]) : 0u;
        *(uint4*)(srow + 768 + 256 * t + cc) = u;
    }
}

// ---------------- tf32 tensor-core GEMM, 3-stage cp.async pipeline ----------------
// out[n,col] = x_t[n,col] + relu( S[n,:kt] @ Wcat[t][:kt,col] )   (bias rides in K)
#define TBM 128
#define TBN 128
#define TBK 16
#define AS_LD 20
#define BS_LD 136
#define NSTG 3

__device__ __forceinline__ void cp16(void* dst_smem, const void* src) {
    unsigned d = (unsigned)__cvta_generic_to_shared(dst_smem);
    asm volatile("cp.async.ca.shared.global [%0], [%1], 16;" :: "r"(d), "l"(src));
}
#define CP_COMMIT()  asm volatile("cp.async.commit_group;")
#define CP_WAIT(n)   asm volatile("cp.async.wait_group %0;" :: "n"(n))

__global__ __launch_bounds__(256) void gemm_tc_kernel(int t, int kt,
                                                      float* __restrict__ dfinal) {
    __shared__ __align__(16) unsigned As[NSTG][TBM * AS_LD];
    __shared__ __align__(16) unsigned Bs[NSTG][TBK * BS_LD];

    const unsigned* Wc = g_Wcat[t];
    const float* xin = g_xs[t];
    float* xout = (t < 3) ? g_xs[t + 1] : dfinal;

    int mblk = blockIdx.x * TBM;
    int nblk = blockIdx.y * TBN;
    int tid  = threadIdx.x;
    int wid  = tid >> 5;
    int lane = tid & 31;
    int wm   = wid & 3;
    int wn   = wid >> 2;
    int g    = lane >> 2;
    int tq   = lane & 3;

    float c[2][8][4];
    #pragma unroll
    for (int mt = 0; mt < 2; mt++)
        #pragma unroll
        for (int nt = 0; nt < 8; nt++)
            #pragma unroll
            for (int i = 0; i < 4; i++) c[mt][nt][i] = 0.f;

    int niter = kt / TBK;

    auto issue = [&](int buf, int kk) {
        #pragma unroll
        for (int l = 0; l < 2; ++l) {
            int ca = tid + l * 256;
            int arow = ca >> 2, aseg = ca & 3;
            cp16(&As[buf][arow * AS_LD + aseg * 4],
                 g_S + (size_t)(mblk + arow) * SK + kk + aseg * 4);
            int brow = ca >> 5, bseg = ca & 31;
            cp16(&Bs[buf][brow * BS_LD + bseg * 4],
                 Wc + (size_t)(kk + brow) * DD + nblk + bseg * 4);
        }
    };

    issue(0, 0); CP_COMMIT();
    if (niter > 1) { issue(1, TBK); CP_COMMIT(); }

    for (int i = 0; i < niter; ++i) {
        int cur = i % NSTG;
        if (i + 2 < niter) {
            issue((i + 2) % NSTG, (i + 2) * TBK);
            CP_COMMIT();
            CP_WAIT(2);
        } else if (i + 1 < niter) {
            CP_WAIT(1);
        } else {
            CP_WAIT(0);
        }
        __syncthreads();

        #pragma unroll
        for (int kc = 0; kc < 2; ++kc) {
            int k0 = kc * 8;
            unsigned a[2][4];
            #pragma unroll
            for (int mt = 0; mt < 2; mt++) {
                int r = wm * 32 + mt * 16 + g;
                a[mt][0] = As[cur][r * AS_LD + k0 + tq];
                a[mt][1] = As[cur][(r + 8) * AS_LD + k0 + tq];
                a[mt][2] = As[cur][r * AS_LD + k0 + tq + 4];
                a[mt][3] = As[cur][(r + 8) * AS_LD + k0 + tq + 4];
            }
            #pragma unroll
            for (int nt = 0; nt < 8; nt++) {
                int nb = wn * 64 + nt * 8;
                unsigned b0 = Bs[cur][(k0 + tq) * BS_LD + nb + g];
                unsigned b1 = Bs[cur][(k0 + tq + 4) * BS_LD + nb + g];
                #pragma unroll
                for (int mt = 0; mt < 2; mt++) {
                    asm volatile(
                        "mma.sync.aligned.m16n8k8.row.col.f32.tf32.tf32.f32 "
                        "{%0,%1,%2,%3}, {%4,%5,%6,%7}, {%8,%9}, {%0,%1,%2,%3};\n"
                        : "+f"(c[mt][nt][0]), "+f"(c[mt][nt][1]),
                          "+f"(c[mt][nt][2]), "+f"(c[mt][nt][3])
                        : "r"(a[mt][0]), "r"(a[mt][1]), "r"(a[mt][2]), "r"(a[mt][3]),
                          "r"(b0), "r"(b1));
                }
            }
        }
        __syncthreads();
    }

    // epilogue: residual + relu
    #pragma unroll
    for (int nt = 0; nt < 8; nt++) {
        int col = nblk + wn * 64 + nt * 8 + 2 * tq;
        #pragma unroll
        for (int mt = 0; mt < 2; mt++) {
            #pragma unroll
            for (int half = 0; half < 2; half++) {
                int r = mblk + wm * 32 + mt * 16 + g + half * 8;
                if (r >= NN) continue;
                float2 xr = *(const float2*)(xin + (size_t)r * DD + col);
                float2 o;
                o.x = xr.x + fmaxf(c[mt][nt][half * 2 + 0], 0.f);
                o.y = xr.y + fmaxf(c[mt][nt][half * 2 + 1], 0.f);
                *(float2*)(xout + (size_t)r * DD + col) = o;
            }
        }
    }
}

// ---------------- driver ----------------
extern "C" void kernel_launch(void* const* d_in, const int* in_sizes, int n_in,
                              void* d_out, int out_size) {
    const float* x      = (const float*)d_in[0];
    const int*   ei     = (const int*)d_in[1];
    const int*   attr   = (const int*)d_in[2];
    const float* W_edge = (const float*)d_in[3];
    const float* b_edge = (const float*)d_in[4];
    const float* W_hop  = (const float*)d_in[5];
    const float* b_hop  = (const float*)d_in[6];
    float* out = (float*)d_out;

    setup_kernel<<<(NN * DD + 255) / 256, 256>>>(x);
    pack_w_kernel<<<(4 * WROWS * DD + 255) / 256, 256>>>(W_edge, b_edge, W_hop, b_hop);
    deg_kernel<<<(EE + 255) / 256, 256>>>(ei);
    scan_kernel<<<1, 1024>>>();
    fill_kernel<<<(EE + 255) / 256, 256>>>(ei, attr);

    dim3 ggrid(NP / TBM, DD / TBN);              // 157 x 2
    for (int t = 0; t < 4; ++t) {
        agg_kernel<<<(NN + 3) / 4, 256>>>(t);
        int kt = 768 + 256 * t + 16;             // includes bias/cnt K-block
        gemm_tc_kernel<<<ggrid, 256>>>(t, kt, out);
    }
}